// round 4
// baseline (speedup 1.0000x reference)
#include <cuda_runtime.h>
#include <cuda_bf16.h>

// CenterLoss: loss = LAMBDA_C * mean_b sum_d (features[b,d] - centers[labels[b],d])^2
// B=65536, D=256, C=100000.
//
// R3: single kernel. Deterministic fixed-point integer atomic accumulation
// (order-invariant) + last-block-finalizes via completion counter. atomicExch
// read-and-resets the accumulator so state self-restores for graph replay.

#define BATCH     65536
#define FEAT_DIM  256
#define LAMBDA_C  1.0

#define WARPS_PER_BLOCK 8
#define ROWS_PER_WARP   8
#define ROWS_PER_BLOCK  (WARPS_PER_BLOCK * ROWS_PER_WARP)      // 64
#define NBLOCKS         (BATCH / ROWS_PER_BLOCK)               // 1024 = single wave

// Fixed-point: block partial <= ~6e3 -> scaled ~2.5e10; total ~1.4e14 << 2^63.
#define FP_SCALE 4194304.0f   /* 2^22 */

__device__ unsigned long long g_acc;   // zero-initialized; reset each replay by finalizer
__device__ unsigned int       g_done;  // completion counter, ditto

__global__ __launch_bounds__(256, 8)
void center_loss_kernel(const float* __restrict__ features,
                        const int*   __restrict__ labels,
                        const float* __restrict__ centers,
                        float*       __restrict__ out) {
    const int warp = threadIdx.x >> 5;
    const int lane = threadIdx.x & 31;
    const int row0 = blockIdx.x * ROWS_PER_BLOCK + warp * ROWS_PER_WARP;

    float acc = 0.0f;

    #pragma unroll
    for (int r = 0; r < ROWS_PER_WARP; r++) {
        const int row = row0 + r;
        const float4* frow = reinterpret_cast<const float4*>(features + (size_t)row * FEAT_DIM);
        const int lab = __ldg(&labels[row]);
        const float4* crow = reinterpret_cast<const float4*>(centers + (size_t)lab * FEAT_DIM);

        // 64 float4 per row / 32 lanes = 2 per lane; 4 independent loads per iter.
        float4 a0 = __ldcs(&frow[lane]);        // features: streaming, never reused
        float4 a1 = __ldcs(&frow[lane + 32]);
        float4 b0 = __ldg(&crow[lane]);         // centers: L2 reuse on label collisions
        float4 b1 = __ldg(&crow[lane + 32]);

        float d;
        d = a0.x - b0.x; acc = fmaf(d, d, acc);
        d = a0.y - b0.y; acc = fmaf(d, d, acc);
        d = a0.z - b0.z; acc = fmaf(d, d, acc);
        d = a0.w - b0.w; acc = fmaf(d, d, acc);
        d = a1.x - b1.x; acc = fmaf(d, d, acc);
        d = a1.y - b1.y; acc = fmaf(d, d, acc);
        d = a1.z - b1.z; acc = fmaf(d, d, acc);
        d = a1.w - b1.w; acc = fmaf(d, d, acc);
    }

    // warp reduce (float)
    #pragma unroll
    for (int off = 16; off > 0; off >>= 1)
        acc += __shfl_xor_sync(0xffffffffu, acc, off);

    __shared__ float s[WARPS_PER_BLOCK];
    if (lane == 0) s[warp] = acc;
    __syncthreads();

    if (threadIdx.x == 0) {
        float t = 0.0f;
        #pragma unroll
        for (int i = 0; i < WARPS_PER_BLOCK; i++) t += s[i];

        // Order-invariant integer accumulation (deterministic).
        atomicAdd(&g_acc, (unsigned long long)llrintf(t * FP_SCALE));
        __threadfence();   // g_acc atomic visible before completion tick

        unsigned int prev = atomicAdd(&g_done, 1u);
        if (prev == NBLOCKS - 1) {
            // All blocks' value-atomics are globally visible. Read+reset in one op.
            unsigned long long v = atomicExch(&g_acc, 0ull);
            double tt = (double)v / (double)FP_SCALE;
            out[0] = (float)(LAMBDA_C * (tt / (double)BATCH));
            g_done = 0u;   // restore for next graph replay
        }
    }
}

extern "C" void kernel_launch(void* const* d_in, const int* in_sizes, int n_in,
                              void* d_out, int out_size) {
    const float* features = (const float*)d_in[0];
    const int*   labels   = (const int*)d_in[1];
    const float* centers  = (const float*)d_in[2];
    float* out = (float*)d_out;

    center_loss_kernel<<<NBLOCKS, 256>>>(features, labels, centers, out);
}

// round 5
// speedup vs baseline: 1.4078x; 1.4078x over previous
#include <cuda_runtime.h>
#include <cuda_bf16.h>

// CenterLoss: loss = LAMBDA_C * mean_b sum_d (features[b,d] - centers[labels[b],d])^2
// B=65536, D=256, C=100000.
//
// R4: revert to proven R2 two-kernel shape (R3 single-kernel fusion regressed:
// per-block __threadfence/CCTL.IVALL + single-wave finalize tail doubled the
// effective DRAM traffic/time). Changes vs R2:
//  - final kernel launched with PDL (programmatic stream serialization) and
//    cudaGridDependencySynchronize() -> launch setup overlaps partial's tail.
//  - partial gets a 40-reg budget (launch_bounds 256,6) so ptxas can front-batch
//    ~2 rows of loads (MLP ~8/warp instead of 4).

#define BATCH     65536
#define FEAT_DIM  256
#define LAMBDA_C  1.0

#define WARPS_PER_BLOCK 8
#define ROWS_PER_WARP   8
#define ROWS_PER_BLOCK  (WARPS_PER_BLOCK * ROWS_PER_WARP)      // 64
#define NBLOCKS         (BATCH / ROWS_PER_BLOCK)               // 1024

// Fixed-point: block partial <= ~6e3 -> scaled ~2.5e10; total ~1.4e14 << 2^63.
// Integer atomics are order-invariant => bitwise-deterministic.
#define FP_SCALE 4194304.0   /* 2^22 */

__device__ unsigned long long g_acc;   // zero-init; reset by final kernel each replay

__global__ __launch_bounds__(256, 6)
void center_loss_partial(const float* __restrict__ features,
                         const int*   __restrict__ labels,
                         const float* __restrict__ centers) {
    const int warp = threadIdx.x >> 5;
    const int lane = threadIdx.x & 31;
    const int row0 = blockIdx.x * ROWS_PER_BLOCK + warp * ROWS_PER_WARP;

    float acc = 0.0f;

    #pragma unroll
    for (int r = 0; r < ROWS_PER_WARP; r++) {
        const int row = row0 + r;
        const float4* frow = reinterpret_cast<const float4*>(features + (size_t)row * FEAT_DIM);
        const int lab = __ldg(&labels[row]);
        const float4* crow = reinterpret_cast<const float4*>(centers + (size_t)lab * FEAT_DIM);

        // 64 float4 per row / 32 lanes = 2 per lane; 4 independent loads per iter,
        // and with the 40-reg budget ptxas can overlap across iterations.
        float4 a0 = __ldcs(&frow[lane]);        // features: streaming, never reused
        float4 a1 = __ldcs(&frow[lane + 32]);
        float4 b0 = __ldg(&crow[lane]);         // centers: L2 reuse on label collisions
        float4 b1 = __ldg(&crow[lane + 32]);

        float d;
        d = a0.x - b0.x; acc = fmaf(d, d, acc);
        d = a0.y - b0.y; acc = fmaf(d, d, acc);
        d = a0.z - b0.z; acc = fmaf(d, d, acc);
        d = a0.w - b0.w; acc = fmaf(d, d, acc);
        d = a1.x - b1.x; acc = fmaf(d, d, acc);
        d = a1.y - b1.y; acc = fmaf(d, d, acc);
        d = a1.z - b1.z; acc = fmaf(d, d, acc);
        d = a1.w - b1.w; acc = fmaf(d, d, acc);
    }

    // warp reduce (float)
    #pragma unroll
    for (int off = 16; off > 0; off >>= 1)
        acc += __shfl_xor_sync(0xffffffffu, acc, off);

    __shared__ float s[WARPS_PER_BLOCK];
    if (lane == 0) s[warp] = acc;
    __syncthreads();

    if (threadIdx.x == 0) {
        float t = 0.0f;
        #pragma unroll
        for (int i = 0; i < WARPS_PER_BLOCK; i++) t += s[i];
        // One order-invariant integer RED per block (no return value used -> REDG).
        atomicAdd(&g_acc, (unsigned long long)llrintf(t * (float)FP_SCALE));
    }
}

__global__ void center_loss_final(float* __restrict__ out) {
    // PDL: launch setup overlapped with the partial kernel; this waits until
    // all partial blocks have completed (implicit trigger at grid completion),
    // which guarantees visibility of their atomics.
    cudaGridDependencySynchronize();

    unsigned long long v = g_acc;
    out[0] = (float)(LAMBDA_C * ((double)v / FP_SCALE / (double)BATCH));
    g_acc = 0ull;   // self-restore for next graph replay
}

extern "C" void kernel_launch(void* const* d_in, const int* in_sizes, int n_in,
                              void* d_out, int out_size) {
    const float* features = (const float*)d_in[0];
    const int*   labels   = (const int*)d_in[1];
    const float* centers  = (const float*)d_in[2];
    float* out = (float*)d_out;

    center_loss_partial<<<NBLOCKS, 256>>>(features, labels, centers);

    // Final kernel with programmatic dependent launch: overlap its launch
    // latency with the partial's execution.
    cudaLaunchConfig_t cfg = {};
    cfg.gridDim  = dim3(1, 1, 1);
    cfg.blockDim = dim3(1, 1, 1);
    cfg.dynamicSmemBytes = 0;
    cfg.stream = 0;  // legacy default stream (same one the <<<>>> launch used)
    cudaLaunchAttribute attrs[1];
    attrs[0].id = cudaLaunchAttributeProgrammaticStreamSerialization;
    attrs[0].val.programmaticStreamSerializationAllowed = 1;
    cfg.attrs = attrs;
    cfg.numAttrs = 1;
    cudaLaunchKernelEx(&cfg, center_loss_final, out);
}